// round 14
// baseline (speedup 1.0000x reference)
#include <cuda_runtime.h>
#include <cuda_bf16.h>

// LinearPositionInterpolation — FINAL (best measured: 23.008 us, reproduced 2x).
//   index: (n,) int32 sorted keypoints (n=129, spacing 32 -> m=4096)
//   value: (batch, n, dim) float32   (batch=32, dim=256)
//   out:   (batch, m, dim) float32, rows p=1..m (excludes start point)
//
// Design (validated over 13 measured rounds):
//  - One (b,seg) tile per 2 blocks; each block: 2 row-lanes x 64 float4 lanes.
//    y0/y1 loaded once per thread; output written as y0 + (y1-y0)*w.
//  - 8192 blocks x 128 threads, 16 blocks/SM — hides L2 store backpressure
//    in graph-replay steady state (occupancy was the decisive lever).
//  - Evict-first (.cs) streaming stores — best among {plain, .cs, .wt,
//    fractional evict_last 0.25/0.5/over-pin}, all A/B-measured.
//  - pow2 shift/mask seg mapping + fully unrolled 8-store fast path for
//    uniform spacing; generic loop keeps any-spacing correctness.
// Sustains ~6.4 TB/s through L2 (~93% of the ~6300 B/cyc path-independent
// LTS cap, which stores cannot bypass) — at the practical hardware ceiling.
// DRAM-traffic reduction via L2 residency pinning was proven NOT to change
// steady-state time (R11/R12), confirming the LTS path as the binder.

static constexpr int DIM    = 256;       // per metadata
static constexpr int DIM4   = DIM / 4;   // 64 float4 lanes per row
static constexpr int HALF   = 2;         // blocks per tile
static constexpr int TPB    = 128;       // 2 row lanes x 64 dim lanes

static constexpr int RLANES_BLK  = TPB / DIM4;        // 2
static constexpr int RLANES_TILE = HALF * RLANES_BLK; // 4
static constexpr int FAST_LEN    = 8 * RLANES_TILE;   // 32 rows

__global__ __launch_bounds__(TPB, 16)
void lpi_kernel(const int* __restrict__ index,
                const float4* __restrict__ value,
                float4* __restrict__ out,
                int n, int m, int seg_shift)   // seg_shift = log2(nseg) or -1
{
    const int nseg = n - 1;
    const int tile = blockIdx.x >> 1;            // (b,seg) tile
    const int half = blockIdx.x & 1;             // which half of row set
    int seg, b;
    if (seg_shift >= 0) {                        // pow2 fast mapping
        seg = tile & (nseg - 1);
        b   = tile >> seg_shift;
    } else {
        seg = tile % nseg;
        b   = tile / nseg;
    }
    const int d  = threadIdx.x & (DIM4 - 1);     // dim lane 0..63
    const int rl = (threadIdx.x >> 6) + half * RLANES_BLK; // row lane 0..3

    const int base = index[0];
    const int x0   = index[seg]     - base;      // L2-hot
    const int x1   = index[seg + 1] - base;
    const int len  = x1 - x0;                    // rows in this segment
    const float inv = 1.0f / (float)len;

    const float4* v = value + (b * n + seg) * DIM4 + d;
    const float4 y0 = __ldg(v);
    const float4 y1 = __ldg(v + DIM4);
    const float4 dy = make_float4(y1.x - y0.x, y1.y - y0.y,
                                  y1.z - y0.z, y1.w - y0.w);

    // output row for p = x0 + pc is (x0 + pc - 1) (0-based, p starts at 1)
    float4* o = out + (b * m + x0 + rl) * DIM4 + d;
    const int ostep = RLANES_TILE * DIM4;

    if (len == FAST_LEN) {
        // uniform spacing: exactly 8 independent stores per thread
        #pragma unroll
        for (int i = 0; i < 8; i++) {
            const float w = (float)(1 + rl + i * RLANES_TILE) * inv;
            float4 r;
            r.x = fmaf(dy.x, w, y0.x);
            r.y = fmaf(dy.y, w, y0.y);
            r.z = fmaf(dy.z, w, y0.z);
            r.w = fmaf(dy.w, w, y0.w);
            __stcs(o + i * ostep, r);            // evict-first streaming store
        }
    } else {
        #pragma unroll 4
        for (int pc = 1 + rl; pc <= len; pc += RLANES_TILE) {
            const float w = (float)pc * inv;
            float4 r;
            r.x = fmaf(dy.x, w, y0.x);
            r.y = fmaf(dy.y, w, y0.y);
            r.z = fmaf(dy.z, w, y0.z);
            r.w = fmaf(dy.w, w, y0.w);
            __stcs(o, r);
            o += ostep;
        }
    }
}

extern "C" void kernel_launch(void* const* d_in, const int* in_sizes, int n_in,
                              void* d_out, int out_size)
{
    const int*    index = (const int*)d_in[0];
    const float4* value = (const float4*)d_in[1];
    float4*       out   = (float4*)d_out;

    const int n     = in_sizes[0];                 // 129
    const int batch = in_sizes[1] / (n * DIM);     // 32
    const int m     = out_size / (batch * DIM);    // 4096

    const int nseg = n - 1;                        // 128 (pow2)
    int seg_shift = -1;
    if ((nseg & (nseg - 1)) == 0) {
        seg_shift = 0;
        while ((1 << seg_shift) < nseg) seg_shift++;
    }

    dim3 grid(batch * nseg * HALF);                // 8192 blocks
    dim3 block(TPB);                               // 128 threads
    lpi_kernel<<<grid, block>>>(index, value, out, n, m, seg_shift);
}

// round 15
// speedup vs baseline: 1.0333x; 1.0333x over previous
#include <cuda_runtime.h>
#include <cuda_bf16.h>

// LinearPositionInterpolation — FINAL (best measured: 23.008 us; identical
// binary re-runs span 23.0–23.8 us, establishing ±0.8 us bench noise).
//   index: (n,) int32 sorted keypoints (n=129, spacing 32 -> m=4096)
//   value: (batch, n, dim) float32   (batch=32, dim=256)
//   out:   (batch, m, dim) float32, rows p=1..m (excludes start point)
//
// Design (validated over 14 measured rounds):
//  - One (b,seg) tile per 2 blocks; each block: 2 row-lanes x 64 float4 lanes.
//    y0/y1 loaded once per thread; output written as y0 + (y1-y0)*w.
//  - 8192 blocks x 128 threads, 16 blocks/SM — occupancy was the decisive
//    lever for hiding L2 store backpressure in graph-replay steady state.
//  - Evict-first (.cs) streaming stores — best among {plain, .cs, .wt,
//    fractional evict_last 0.25/0.5/over-pin}, all A/B-measured.
//  - pow2 shift/mask seg mapping + fully unrolled 8-store fast path for
//    uniform spacing; generic loop keeps any-spacing correctness.
// Sustains ~6.4 TB/s through L2 (~93% of the ~6300 B/cyc path-independent
// LTS cap, which stores cannot bypass). L2-residency pinning cut DRAM
// traffic up to 50% with zero time change (R11/R12), proving the LTS path
// is the binder — the kernel is at the practical hardware ceiling.

static constexpr int DIM    = 256;       // per metadata
static constexpr int DIM4   = DIM / 4;   // 64 float4 lanes per row
static constexpr int HALF   = 2;         // blocks per tile
static constexpr int TPB    = 128;       // 2 row lanes x 64 dim lanes

static constexpr int RLANES_BLK  = TPB / DIM4;        // 2
static constexpr int RLANES_TILE = HALF * RLANES_BLK; // 4
static constexpr int FAST_LEN    = 8 * RLANES_TILE;   // 32 rows

__global__ __launch_bounds__(TPB, 16)
void lpi_kernel(const int* __restrict__ index,
                const float4* __restrict__ value,
                float4* __restrict__ out,
                int n, int m, int seg_shift)   // seg_shift = log2(nseg) or -1
{
    const int nseg = n - 1;
    const int tile = blockIdx.x >> 1;            // (b,seg) tile
    const int half = blockIdx.x & 1;             // which half of row set
    int seg, b;
    if (seg_shift >= 0) {                        // pow2 fast mapping
        seg = tile & (nseg - 1);
        b   = tile >> seg_shift;
    } else {
        seg = tile % nseg;
        b   = tile / nseg;
    }
    const int d  = threadIdx.x & (DIM4 - 1);     // dim lane 0..63
    const int rl = (threadIdx.x >> 6) + half * RLANES_BLK; // row lane 0..3

    const int base = index[0];
    const int x0   = index[seg]     - base;      // L2-hot
    const int x1   = index[seg + 1] - base;
    const int len  = x1 - x0;                    // rows in this segment
    const float inv = 1.0f / (float)len;

    const float4* v = value + (b * n + seg) * DIM4 + d;
    const float4 y0 = __ldg(v);
    const float4 y1 = __ldg(v + DIM4);
    const float4 dy = make_float4(y1.x - y0.x, y1.y - y0.y,
                                  y1.z - y0.z, y1.w - y0.w);

    // output row for p = x0 + pc is (x0 + pc - 1) (0-based, p starts at 1)
    float4* o = out + (b * m + x0 + rl) * DIM4 + d;
    const int ostep = RLANES_TILE * DIM4;

    if (len == FAST_LEN) {
        // uniform spacing: exactly 8 independent stores per thread
        #pragma unroll
        for (int i = 0; i < 8; i++) {
            const float w = (float)(1 + rl + i * RLANES_TILE) * inv;
            float4 r;
            r.x = fmaf(dy.x, w, y0.x);
            r.y = fmaf(dy.y, w, y0.y);
            r.z = fmaf(dy.z, w, y0.z);
            r.w = fmaf(dy.w, w, y0.w);
            __stcs(o + i * ostep, r);            // evict-first streaming store
        }
    } else {
        #pragma unroll 4
        for (int pc = 1 + rl; pc <= len; pc += RLANES_TILE) {
            const float w = (float)pc * inv;
            float4 r;
            r.x = fmaf(dy.x, w, y0.x);
            r.y = fmaf(dy.y, w, y0.y);
            r.z = fmaf(dy.z, w, y0.z);
            r.w = fmaf(dy.w, w, y0.w);
            __stcs(o, r);
            o += ostep;
        }
    }
}

extern "C" void kernel_launch(void* const* d_in, const int* in_sizes, int n_in,
                              void* d_out, int out_size)
{
    const int*    index = (const int*)d_in[0];
    const float4* value = (const float4*)d_in[1];
    float4*       out   = (float4*)d_out;

    const int n     = in_sizes[0];                 // 129
    const int batch = in_sizes[1] / (n * DIM);     // 32
    const int m     = out_size / (batch * DIM);    // 4096

    const int nseg = n - 1;                        // 128 (pow2)
    int seg_shift = -1;
    if ((nseg & (nseg - 1)) == 0) {
        seg_shift = 0;
        while ((1 << seg_shift) < nseg) seg_shift++;
    }

    dim3 grid(batch * nseg * HALF);                // 8192 blocks
    dim3 block(TPB);                               // 128 threads
    lpi_kernel<<<grid, block>>>(index, value, out, n, m, seg_shift);
}